// round 4
// baseline (speedup 1.0000x reference)
#include <cuda_runtime.h>
#include <cstdint>

// ---------------------------------------------------------------------------
// PatternBasedV2_260: pattern-hash EmbeddingBag(max_norm=1) + 3-layer MLP
// Inputs (metadata order):
//   0: x    int32  [8192, 2, 8, 8]
//   1: emb  f32    [225990, 256]
//   2: w1 [256,64]  3: b1[64]  4: w2 [64,32]  5: b2[32]  6: w3 [32,1]  7: b3[1]
// Output: f32 [8192, 1]
//
// R2 design (second resubmit after broker infra failures): half-warp row
// processing (2 rows/warp in flight, 4-shfl reduce shared by both rows,
// 8 independent LDG.128 per iter), tables computed inline from compile-time
// masks (no init kernel).
// ---------------------------------------------------------------------------

#define NUM_PATTERNS 16
#define FRONT 256
#define MID 64
#define BACK 32

__device__ __forceinline__ unsigned long long pat_mask(int p) {
    const unsigned long long P[NUM_PATTERNS] = {
        16639ULL, 65280ULL, 16711680ULL, 4278190080ULL, 3871ULL, 198415ULL,
        4345695256ULL, 1108169199648ULL, 283691315109952ULL,
        72624976668147840ULL, 7357ULL, 135137027ULL, 460551ULL, 1279ULL,
        134614787ULL, 33693443ULL};
    return P[p];
}

__global__ __launch_bounds__(256) void pattern_forward_kernel(
    const int* __restrict__ x, const float* __restrict__ emb,
    const float* __restrict__ w1, const float* __restrict__ b1,
    const float* __restrict__ w2, const float* __restrict__ b2,
    const float* __restrict__ w3, const float* __restrict__ b3,
    float* __restrict__ out)
{
    __shared__ int v[64];
    __shared__ int sidx[128];
    __shared__ float wacc[16][FRONT];   // one partial per half-warp
    __shared__ float m[FRONT];
    __shared__ float h1[MID];
    __shared__ float h2[BACK];

    const int b = blockIdx.x;
    const int t = threadIdx.x;
    const int warp = t >> 5, lane = t & 31;
    const int half = lane >> 4, hl = lane & 15;

    // 1) board cells: v = plane0 + 2*plane1  (values in {0,1,2})
    const int* xb = x + (size_t)b * 128;
    if (t < 64) v[t] = xb[t] + 2 * xb[64 + t];
    __syncthreads();

    // 2) 128 pattern indices (8 symmetries x 16 patterns), tables inline.
    if (t < 128) {
        const int k = t >> 4, p = t & 15;
        // bias = sum over q<p of 3^popcount(mask_q)
        int bias = 0;
        #pragma unroll
        for (int q = 0; q < NUM_PATTERNS; q++) {
            if (q < p) {
                int n = __popcll(pat_mask(q));
                int pw = 1;
                for (int i = 0; i < n; i++) pw *= 3;
                bias += pw;
            }
        }
        int s = bias;
        int w = 1;
        unsigned long long msk = pat_mask(p);
        while (msk) {
            int pos = __ffsll((long long)msk) - 1;
            msk &= msk - 1;
            int R = pos >> 3, C = pos & 7;
            int C2 = (k & 4) ? 7 - C : C;
            int R2 = (k & 2) ? 7 - R : R;
            int posk = (k & 1) ? (C2 * 8 + R2) : (R2 * 8 + C2);
            s += w * v[posk];
            w *= 3;
        }
        sidx[t] = s;
    }
    __syncthreads();

    // 3) gather + conditional renorm + sum.
    //    Warp w owns rows [16w,16w+16); each iter: half0 -> row 2i, half1 -> 2i+1.
    //    Lane covers float4 slots hl+16j (j=0..3) of its row => dims 4*(hl+16j)..+3
    const float4* __restrict__ embv = (const float4*)emb;
    const int base = warp * 16;

    float4 acc[4];
    #pragma unroll
    for (int j = 0; j < 4; j++) acc[j] = make_float4(0.f, 0.f, 0.f, 0.f);

    int r = sidx[base + half] * 64;   // 225990*64 < 2^31
    float4 cur[4];
    #pragma unroll
    for (int j = 0; j < 4; j++) cur[j] = embv[r + hl + 16 * j];

    #pragma unroll
    for (int i = 0; i < 8; i++) {
        float4 nxt[4];
        if (i < 7) {
            int nr = sidx[base + 2 * (i + 1) + half] * 64;
            #pragma unroll
            for (int j = 0; j < 4; j++) nxt[j] = embv[nr + hl + 16 * j];
        }
        float ss = 0.f;
        #pragma unroll
        for (int j = 0; j < 4; j++) {
            ss = fmaf(cur[j].x, cur[j].x, ss);
            ss = fmaf(cur[j].y, cur[j].y, ss);
            ss = fmaf(cur[j].z, cur[j].z, ss);
            ss = fmaf(cur[j].w, cur[j].w, ss);
        }
        // width-16 butterfly: stays within each half-warp
        ss += __shfl_xor_sync(0xffffffffu, ss, 8);
        ss += __shfl_xor_sync(0xffffffffu, ss, 4);
        ss += __shfl_xor_sync(0xffffffffu, ss, 2);
        ss += __shfl_xor_sync(0xffffffffu, ss, 1);
        float scale = 1.0f;
        if (ss > 1.0f) scale = __fdividef(1.0f, sqrtf(ss) + 1e-7f);
        #pragma unroll
        for (int j = 0; j < 4; j++) {
            acc[j].x = fmaf(scale, cur[j].x, acc[j].x);
            acc[j].y = fmaf(scale, cur[j].y, acc[j].y);
            acc[j].z = fmaf(scale, cur[j].z, acc[j].z);
            acc[j].w = fmaf(scale, cur[j].w, acc[j].w);
        }
        #pragma unroll
        for (int j = 0; j < 4; j++) cur[j] = nxt[j];
    }
    {
        float4* wa = (float4*)wacc[warp * 2 + half];
        #pragma unroll
        for (int j = 0; j < 4; j++) wa[hl + 16 * j] = acc[j];
    }
    __syncthreads();

    // 4) reduce the 16 half-warp partials -> m[256]
    {
        float s = 0.f;
        #pragma unroll
        for (int p = 0; p < 16; p++) s += wacc[p][t];
        m[t] = s;
    }
    __syncthreads();

    // 5) MLP: 256 -> 64 (relu) -> 32 (relu) -> 1
    if (t < MID) {
        float acc1 = b1[t];
        #pragma unroll 8
        for (int i = 0; i < FRONT; i++) acc1 = fmaf(m[i], w1[i * MID + t], acc1);
        h1[t] = fmaxf(acc1, 0.f);
    }
    __syncthreads();
    if (t < BACK) {
        float acc2 = b2[t];
        #pragma unroll 8
        for (int i = 0; i < MID; i++) acc2 = fmaf(h1[i], w2[i * BACK + t], acc2);
        h2[t] = fmaxf(acc2, 0.f);
    }
    __syncthreads();
    if (t == 0) {
        float acc3 = b3[0];
        #pragma unroll
        for (int i = 0; i < BACK; i++) acc3 = fmaf(h2[i], w3[i], acc3);
        out[b] = acc3;
    }
}

extern "C" void kernel_launch(void* const* d_in, const int* in_sizes, int n_in,
                              void* d_out, int out_size)
{
    const int* x = (const int*)d_in[0];
    const float* emb = (const float*)d_in[1];
    const float* w1 = (const float*)d_in[2];
    const float* b1 = (const float*)d_in[3];
    const float* w2 = (const float*)d_in[4];
    const float* b2 = (const float*)d_in[5];
    const float* w3 = (const float*)d_in[6];
    const float* b3 = (const float*)d_in[7];
    float* out = (float*)d_out;

    const int batch = in_sizes[0] / 128;  // [B,2,8,8] int32

    pattern_forward_kernel<<<batch, 256>>>(x, emb, w1, b1, w2, b2, w3, b3, out);
}

// round 5
// speedup vs baseline: 1.7290x; 1.7290x over previous
#include <cuda_runtime.h>
#include <cstdint>

// ---------------------------------------------------------------------------
// PatternBasedV2_260: pattern-hash EmbeddingBag(max_norm=1) + 3-layer MLP
// Inputs: 0:x int32[8192,2,8,8] 1:emb f32[225990,256] 2:w1[256,64] 3:b1[64]
//         4:w2[64,32] 5:b2[32] 6:w3[32,1] 7:b3[1]   Output: f32[8192,1]
//
// R5: R1 full-warp layout + prefetch depth 3 (reg-capped to keep 5 blocks/SM),
// inline-mask index hashing, fully parallelized MLP tail.
// ---------------------------------------------------------------------------

#define NUM_PATTERNS 16
#define FRONT 256
#define MID 64
#define BACK 32

__device__ __forceinline__ unsigned long long pat_mask(int p) {
    const unsigned long long P[NUM_PATTERNS] = {
        16639ULL, 65280ULL, 16711680ULL, 4278190080ULL, 3871ULL, 198415ULL,
        4345695256ULL, 1108169199648ULL, 283691315109952ULL,
        72624976668147840ULL, 7357ULL, 135137027ULL, 460551ULL, 1279ULL,
        134614787ULL, 33693443ULL};
    return P[p];
}

__global__ __launch_bounds__(256, 5) void pattern_forward_kernel(
    const int* __restrict__ x, const float* __restrict__ emb,
    const float* __restrict__ w1, const float* __restrict__ b1,
    const float* __restrict__ w2, const float* __restrict__ b2,
    const float* __restrict__ w3, const float* __restrict__ b3,
    float* __restrict__ out)
{
    __shared__ int v[64];
    __shared__ int sidx[128];
    __shared__ float wacc[8][FRONT];    // per-warp partial bag sums
    __shared__ float m[FRONT];
    __shared__ float p1[4][MID];        // layer1 partials
    __shared__ float p2[8][BACK];       // layer2 partials
    __shared__ float h1[MID];
    __shared__ float h2[BACK];

    const int b = blockIdx.x;
    const int t = threadIdx.x;
    const int warp = t >> 5, lane = t & 31;

    // 1) board cells: v = plane0 + 2*plane1 (values in {0,1,2})
    const int* xb = x + (size_t)b * 128;
    if (t < 64) v[t] = xb[t] + 2 * xb[64 + t];
    __syncthreads();

    // 2) 128 pattern indices (8 symmetries x 16 patterns), inline tables.
    if (t < 128) {
        const int k = t >> 4, p = t & 15;
        int bias = 0;
        #pragma unroll
        for (int q = 0; q < NUM_PATTERNS; q++) {
            if (q < p) {
                int n = __popcll(pat_mask(q));
                int pw = 1;
                for (int i = 0; i < n; i++) pw *= 3;
                bias += pw;
            }
        }
        int s = bias;
        int w = 1;
        unsigned long long msk = pat_mask(p);
        while (msk) {
            int pos = __ffsll((long long)msk) - 1;
            msk &= msk - 1;
            int R = pos >> 3, C = pos & 7;
            int C2 = (k & 4) ? 7 - C : C;
            int R2 = (k & 2) ? 7 - R : R;
            int posk = (k & 1) ? (C2 * 8 + R2) : (R2 * 8 + C2);
            s += w * v[posk];
            w *= 3;
        }
        sidx[t] = s;
    }
    __syncthreads();

    // 3) gather + conditional renorm + sum. Warp w owns rows [16w, 16w+16).
    //    Lane covers float4 slots {lane, 32+lane} => dims 4l..4l+3, 128+4l..+3.
    //    Software pipeline depth 3: rows i, i+1, i+2 in flight.
    const float4* __restrict__ embv = (const float4*)emb;
    const int base = warp * 16;

    float4 acc0 = make_float4(0.f, 0.f, 0.f, 0.f);
    float4 acc1 = make_float4(0.f, 0.f, 0.f, 0.f);

    int r0 = sidx[base + 0] * 64;     // 225990*64 < 2^31
    int r1 = sidx[base + 1] * 64;
    float4 a0 = embv[r0 + lane],      c0 = embv[r0 + 32 + lane];
    float4 a1 = embv[r1 + lane],      c1 = embv[r1 + 32 + lane];

    #pragma unroll
    for (int i = 0; i < 16; i++) {
        float4 a2, c2;
        if (i < 14) {
            int r2 = sidx[base + i + 2] * 64;
            a2 = embv[r2 + lane];
            c2 = embv[r2 + 32 + lane];
        }
        // two parallel 4-FMA chains, then join
        float s1 = a0.x * a0.x;
        float s2 = c0.x * c0.x;
        s1 = fmaf(a0.y, a0.y, s1);  s2 = fmaf(c0.y, c0.y, s2);
        s1 = fmaf(a0.z, a0.z, s1);  s2 = fmaf(c0.z, c0.z, s2);
        s1 = fmaf(a0.w, a0.w, s1);  s2 = fmaf(c0.w, c0.w, s2);
        float ss = s1 + s2;
        #pragma unroll
        for (int o = 16; o > 0; o >>= 1)
            ss += __shfl_xor_sync(0xffffffffu, ss, o);
        float scale = 1.0f;
        if (ss > 1.0f) scale = __fdividef(1.0f, sqrtf(ss) + 1e-7f);
        acc0.x = fmaf(scale, a0.x, acc0.x);
        acc0.y = fmaf(scale, a0.y, acc0.y);
        acc0.z = fmaf(scale, a0.z, acc0.z);
        acc0.w = fmaf(scale, a0.w, acc0.w);
        acc1.x = fmaf(scale, c0.x, acc1.x);
        acc1.y = fmaf(scale, c0.y, acc1.y);
        acc1.z = fmaf(scale, c0.z, acc1.z);
        acc1.w = fmaf(scale, c0.w, acc1.w);
        a0 = a1; c0 = c1;
        a1 = a2; c1 = c2;
    }
    {
        float4* wa = (float4*)wacc[warp];
        wa[lane] = acc0;
        wa[32 + lane] = acc1;
    }
    __syncthreads();

    // 4) reduce 8 warp partials -> m[256]
    {
        float s = 0.f;
        #pragma unroll
        for (int wg = 0; wg < 8; wg++) s += wacc[wg][t];
        m[t] = s;
    }
    __syncthreads();

    // 5) MLP, all 8 warps active.
    // Layer1 (256->64): output o = lane + 32*(warp&1), part p = warp>>1
    //   each thread sums i in [64p, 64p+64); w1 reads coalesced (row-major).
    {
        const int o = lane + 32 * (warp & 1);
        const int p = warp >> 1;
        float s = 0.f;
        #pragma unroll 8
        for (int i = 0; i < 64; i++) {
            int ii = 64 * p + i;
            s = fmaf(m[ii], w1[ii * MID + o], s);
        }
        p1[p][o] = s;
    }
    __syncthreads();
    if (t < MID) {
        float s = b1[t] + p1[0][t] + p1[1][t] + p1[2][t] + p1[3][t];
        h1[t] = fmaxf(s, 0.f);
    }
    __syncthreads();
    // Layer2 (64->32): output o = lane (only lanes<32 used), part p = warp
    //   each thread sums i in [8p, 8p+8); w2 reads coalesced.
    {
        const int o = lane;
        const int p = warp;
        float s = 0.f;
        #pragma unroll
        for (int i = 0; i < 8; i++) {
            int ii = 8 * p + i;
            s = fmaf(h1[ii], w2[ii * BACK + o], s);
        }
        p2[p][o] = s;
    }
    __syncthreads();
    // Layer3 (32->1): warp 0 reduces
    if (warp == 0) {
        float s = b2[lane];
        #pragma unroll
        for (int p = 0; p < 8; p++) s += p2[p][lane];
        float h = fmaxf(s, 0.f);
        float part = h * w3[lane];
        #pragma unroll
        for (int o = 16; o > 0; o >>= 1)
            part += __shfl_xor_sync(0xffffffffu, part, o);
        if (lane == 0) out[b] = part + b3[0];
    }
}

extern "C" void kernel_launch(void* const* d_in, const int* in_sizes, int n_in,
                              void* d_out, int out_size)
{
    const int* x = (const int*)d_in[0];
    const float* emb = (const float*)d_in[1];
    const float* w1 = (const float*)d_in[2];
    const float* b1 = (const float*)d_in[3];
    const float* w2 = (const float*)d_in[4];
    const float* b2 = (const float*)d_in[5];
    const float* w3 = (const float*)d_in[6];
    const float* b3 = (const float*)d_in[7];
    float* out = (float*)d_out;

    const int batch = in_sizes[0] / 128;  // [B,2,8,8] int32

    pattern_forward_kernel<<<batch, 256>>>(x, emb, w1, b1, w2, b2, w3, b3, out);
}

// round 6
// speedup vs baseline: 1.8038x; 1.0433x over previous
#include <cuda_runtime.h>
#include <cstdint>

// ---------------------------------------------------------------------------
// PatternBasedV2_260: pattern-hash EmbeddingBag(max_norm=1) + 3-layer MLP
// Inputs: 0:x int32[8192,2,8,8] 1:emb f32[225990,256] 2:w1[256,64] 3:b1[64]
//         4:w2[64,32] 5:b2[32] 6:w3[32,1] 7:b3[1]   Output: f32[8192,1]
//
// R6: R5 (depth-3 register pipeline, 5 blocks/SM) + register-free L2 prefetch
// with ~6-row lead: one predicated prefetch instruction per row-half covers
// all 8x128B lines via lanes 0-7.
// ---------------------------------------------------------------------------

#define NUM_PATTERNS 16
#define FRONT 256
#define MID 64
#define BACK 32

__device__ __forceinline__ unsigned long long pat_mask(int p) {
    const unsigned long long P[NUM_PATTERNS] = {
        16639ULL, 65280ULL, 16711680ULL, 4278190080ULL, 3871ULL, 198415ULL,
        4345695256ULL, 1108169199648ULL, 283691315109952ULL,
        72624976668147840ULL, 7357ULL, 135137027ULL, 460551ULL, 1279ULL,
        134614787ULL, 33693443ULL};
    return P[p];
}

__device__ __forceinline__ void prefetch_row_l2(const float* emb, int rowelts,
                                                int lane) {
    // Cover the 1KB row (8 x 128B lines) with lanes 0..7.
    if (lane < 8) {
        const char* p = (const char*)(emb + rowelts) + lane * 128;
        asm volatile("prefetch.global.L2 [%0];" :: "l"(p));
    }
}

__global__ __launch_bounds__(256, 5) void pattern_forward_kernel(
    const int* __restrict__ x, const float* __restrict__ emb,
    const float* __restrict__ w1, const float* __restrict__ b1,
    const float* __restrict__ w2, const float* __restrict__ b2,
    const float* __restrict__ w3, const float* __restrict__ b3,
    float* __restrict__ out)
{
    __shared__ int v[64];
    __shared__ int sidx[128];
    __shared__ float wacc[8][FRONT];    // per-warp partial bag sums
    __shared__ float m[FRONT];
    __shared__ float p1[4][MID];        // layer1 partials
    __shared__ float p2[8][BACK];       // layer2 partials
    __shared__ float h1[MID];

    const int b = blockIdx.x;
    const int t = threadIdx.x;
    const int warp = t >> 5, lane = t & 31;

    // 1) board cells: v = plane0 + 2*plane1 (values in {0,1,2})
    const int* xb = x + (size_t)b * 128;
    if (t < 64) v[t] = xb[t] + 2 * xb[64 + t];
    __syncthreads();

    // 2) 128 pattern indices (8 symmetries x 16 patterns), inline tables.
    if (t < 128) {
        const int k = t >> 4, p = t & 15;
        int bias = 0;
        #pragma unroll
        for (int q = 0; q < NUM_PATTERNS; q++) {
            if (q < p) {
                int n = __popcll(pat_mask(q));
                int pw = 1;
                for (int i = 0; i < n; i++) pw *= 3;
                bias += pw;
            }
        }
        int s = bias;
        int w = 1;
        unsigned long long msk = pat_mask(p);
        while (msk) {
            int pos = __ffsll((long long)msk) - 1;
            msk &= msk - 1;
            int R = pos >> 3, C = pos & 7;
            int C2 = (k & 4) ? 7 - C : C;
            int R2 = (k & 2) ? 7 - R : R;
            int posk = (k & 1) ? (C2 * 8 + R2) : (R2 * 8 + C2);
            s += w * v[posk];
            w *= 3;
        }
        sidx[t] = s;
    }
    __syncthreads();

    // 3) gather + conditional renorm + sum. Warp w owns rows [16w, 16w+16).
    //    Lane covers float4 slots {lane, 32+lane}.
    //    Register pipeline depth 3 (LDG at i+2) + L2 prefetch at i+8.
    const float4* __restrict__ embv = (const float4*)emb;
    const int base = warp * 16;

    // L2 prefetch for rows 2..7 (rows 0,1 are loaded immediately below).
    #pragma unroll
    for (int i = 2; i < 8; i++)
        prefetch_row_l2(emb, sidx[base + i] * 256, lane);

    float4 acc0 = make_float4(0.f, 0.f, 0.f, 0.f);
    float4 acc1 = make_float4(0.f, 0.f, 0.f, 0.f);

    int r0 = sidx[base + 0] * 64;     // float4 units; 225990*64 < 2^31
    int r1 = sidx[base + 1] * 64;
    float4 a0 = embv[r0 + lane],      c0 = embv[r0 + 32 + lane];
    float4 a1 = embv[r1 + lane],      c1 = embv[r1 + 32 + lane];

    #pragma unroll
    for (int i = 0; i < 16; i++) {
        if (i < 8)
            prefetch_row_l2(emb, sidx[base + i + 8] * 256, lane);
        float4 a2, c2;
        if (i < 14) {
            int r2 = sidx[base + i + 2] * 64;
            a2 = embv[r2 + lane];
            c2 = embv[r2 + 32 + lane];
        }
        // two parallel 4-FMA chains, then join
        float s1 = a0.x * a0.x;
        float s2 = c0.x * c0.x;
        s1 = fmaf(a0.y, a0.y, s1);  s2 = fmaf(c0.y, c0.y, s2);
        s1 = fmaf(a0.z, a0.z, s1);  s2 = fmaf(c0.z, c0.z, s2);
        s1 = fmaf(a0.w, a0.w, s1);  s2 = fmaf(c0.w, c0.w, s2);
        float ss = s1 + s2;
        #pragma unroll
        for (int o = 16; o > 0; o >>= 1)
            ss += __shfl_xor_sync(0xffffffffu, ss, o);
        float scale = 1.0f;
        if (ss > 1.0f) scale = __fdividef(1.0f, sqrtf(ss) + 1e-7f);
        acc0.x = fmaf(scale, a0.x, acc0.x);
        acc0.y = fmaf(scale, a0.y, acc0.y);
        acc0.z = fmaf(scale, a0.z, acc0.z);
        acc0.w = fmaf(scale, a0.w, acc0.w);
        acc1.x = fmaf(scale, c0.x, acc1.x);
        acc1.y = fmaf(scale, c0.y, acc1.y);
        acc1.z = fmaf(scale, c0.z, acc1.z);
        acc1.w = fmaf(scale, c0.w, acc1.w);
        a0 = a1; c0 = c1;
        a1 = a2; c1 = c2;
    }
    {
        float4* wa = (float4*)wacc[warp];
        wa[lane] = acc0;
        wa[32 + lane] = acc1;
    }
    __syncthreads();

    // 4) reduce 8 warp partials -> m[256]
    {
        float s = 0.f;
        #pragma unroll
        for (int wg = 0; wg < 8; wg++) s += wacc[wg][t];
        m[t] = s;
    }
    __syncthreads();

    // 5) MLP, all 8 warps active.
    // Layer1 (256->64): output o = lane + 32*(warp&1), part p = warp>>1
    {
        const int o = lane + 32 * (warp & 1);
        const int p = warp >> 1;
        float s = 0.f;
        #pragma unroll 8
        for (int i = 0; i < 64; i++) {
            int ii = 64 * p + i;
            s = fmaf(m[ii], w1[ii * MID + o], s);
        }
        p1[p][o] = s;
    }
    __syncthreads();
    if (t < MID) {
        float s = b1[t] + p1[0][t] + p1[1][t] + p1[2][t] + p1[3][t];
        h1[t] = fmaxf(s, 0.f);
    }
    __syncthreads();
    // Layer2 (64->32): output o = lane, part p = warp; sums i in [8p, 8p+8).
    {
        const int o = lane;
        const int p = warp;
        float s = 0.f;
        #pragma unroll
        for (int i = 0; i < 8; i++) {
            int ii = 8 * p + i;
            s = fmaf(h1[ii], w2[ii * BACK + o], s);
        }
        p2[p][o] = s;
    }
    __syncthreads();
    // Layer3 (32->1): warp 0 reduces
    if (warp == 0) {
        float s = b2[lane];
        #pragma unroll
        for (int p = 0; p < 8; p++) s += p2[p][lane];
        float h = fmaxf(s, 0.f);
        float part = h * w3[lane];
        #pragma unroll
        for (int o = 16; o > 0; o >>= 1)
            part += __shfl_xor_sync(0xffffffffu, part, o);
        if (lane == 0) out[b] = part + b3[0];
    }
}

extern "C" void kernel_launch(void* const* d_in, const int* in_sizes, int n_in,
                              void* d_out, int out_size)
{
    const int* x = (const int*)d_in[0];
    const float* emb = (const float*)d_in[1];
    const float* w1 = (const float*)d_in[2];
    const float* b1 = (const float*)d_in[3];
    const float* w2 = (const float*)d_in[4];
    const float* b2 = (const float*)d_in[5];
    const float* w3 = (const float*)d_in[6];
    const float* b3 = (const float*)d_in[7];
    float* out = (float*)d_out;

    const int batch = in_sizes[0] / 128;  // [B,2,8,8] int32

    pattern_forward_kernel<<<batch, 256>>>(x, emb, w1, b1, w2, b2, w3, b3, out);
}